// round 1
// baseline (speedup 1.0000x reference)
#include <cuda_runtime.h>
#include <math.h>

#define B_ 256
#define M_ 64
#define N_ 32
#define D_ 128
#define T_ 64
#define L_ 128

// Scratch (allocation-free: __device__ globals)
__device__ float g_WT[(size_t)M_ * N_ * T_ * D_];      // entmax weights, [mn][t][d]  (67 MB)
__device__ float g_priors[(size_t)N_ * B_ * M_ * T_];  // priors, [n][b][m][t]        (134 MB)
__device__ float g_lh[L_ * T_];                        // normalized leaves

// ---------------------------------------------------------------------------
// K0: normalize routing_leaves rows
// ---------------------------------------------------------------------------
__global__ void k_leaves(const float* __restrict__ leaves) {
    int l = threadIdx.x;
    if (l < L_) {
        float s = 0.f;
        #pragma unroll
        for (int t = 0; t < T_; ++t) { float v = leaves[l * T_ + t]; s = fmaf(v, v, s); }
        float inv = 1.0f / fmaxf(sqrtf(s), 1e-12f);
        #pragma unroll
        for (int t = 0; t < T_; ++t) g_lh[l * T_ + t] = leaves[l * T_ + t] * inv;
    }
}

// ---------------------------------------------------------------------------
// K1: exact 1.5-entmax over D per (m,n,t) column via bisection on
//     f(tau) = sum max(z - tau, 0)^2 = 1,  tau in [-1, 0] after z = x/2 - max(x/2).
//     One thread per t-column (column in registers). Writes transposed [t][d].
// ---------------------------------------------------------------------------
__global__ __launch_bounds__(64) void k_entmax(const float* __restrict__ rw) {
    __shared__ float sm[D_ * 65];  // [d][t], pad 65 (conflict-free columns)
    int mn = blockIdx.x;
    const float* src = rw + (size_t)mn * D_ * T_;
    for (int i = threadIdx.x; i < D_ * T_; i += 64) {
        int d = i >> 6, t = i & 63;
        sm[d * 65 + t] = src[i];
    }
    __syncthreads();

    int t = threadIdx.x;
    float z[D_];
    float mx = -3.0e38f;
    #pragma unroll
    for (int d = 0; d < D_; ++d) { z[d] = sm[d * 65 + t]; mx = fmaxf(mx, z[d]); }
    mx *= 0.5f;
    #pragma unroll
    for (int d = 0; d < D_; ++d) z[d] = 0.5f * z[d] - mx;

    float lo = -1.0f, hi = 0.0f;
    #pragma unroll 1
    for (int it = 0; it < 24; ++it) {
        float mid = 0.5f * (lo + hi);
        float s0 = 0.f, s1 = 0.f, s2 = 0.f, s3 = 0.f;
        #pragma unroll
        for (int d = 0; d < D_; d += 4) {
            float a0 = fmaxf(z[d + 0] - mid, 0.f); s0 = fmaf(a0, a0, s0);
            float a1 = fmaxf(z[d + 1] - mid, 0.f); s1 = fmaf(a1, a1, s1);
            float a2 = fmaxf(z[d + 2] - mid, 0.f); s2 = fmaf(a2, a2, s2);
            float a3 = fmaxf(z[d + 3] - mid, 0.f); s3 = fmaf(a3, a3, s3);
        }
        float s = (s0 + s1) + (s2 + s3);
        if (s >= 1.0f) lo = mid; else hi = mid;
    }
    float tau = 0.5f * (lo + hi);

    // write weights back into own column, then cooperative transposed store
    #pragma unroll
    for (int d = 0; d < D_; ++d) { float a = fmaxf(z[d] - tau, 0.f); sm[d * 65 + t] = a * a; }
    __syncthreads();
    float* dst = g_WT + (size_t)mn * T_ * D_;
    for (int i = threadIdx.x; i < T_ * D_; i += 64) {
        int tt = i >> 7, d = i & 127;
        dst[i] = sm[d * 65 + tt];  // [t][d], coalesced global, conflict-free smem
    }
}

// ---------------------------------------------------------------------------
// K2: priors[b,m,n,t] = sum_d x[b,m,d] * W[m,n,d,t].
//     One block per (m,n): GEMM [256 x 64] = X[256 x 128] * WT^T.
//     WT slab in smem (pad 132 -> float4 row stride 33, odd => conflict-free).
//     Thread tile: 4 b x 4 t (t strided by 16 for bank-conflict-free LDS.128).
//     Output layout [n][b][m][t] for the routing kernel.
// ---------------------------------------------------------------------------
__global__ __launch_bounds__(256) void k_priors(const float* __restrict__ x) {
    __shared__ float ws[T_ * 132];
    int mn = blockIdx.x;
    int m = mn >> 5, n = mn & 31;  // N_ = 32
    {
        const float* wsrc = g_WT + (size_t)mn * T_ * D_;
        for (int i = threadIdx.x; i < T_ * D_; i += 256) {
            int t = i >> 7, d = i & 127;
            ws[t * 132 + d] = wsrc[i];
        }
    }
    __syncthreads();
    const float4* ws4 = reinterpret_cast<const float4*>(ws);  // row stride 33 float4
    int tx = threadIdx.x & 15;   // t-group: t = tx + 16*ti
    int ty = threadIdx.x >> 4;   // b-group

    #pragma unroll 1
    for (int chunk = 0; chunk < 4; ++chunk) {
        int b0 = chunk * 64 + ty * 4;
        float acc[4][4];
        #pragma unroll
        for (int bi = 0; bi < 4; ++bi)
            #pragma unroll
            for (int ti = 0; ti < 4; ++ti) acc[bi][ti] = 0.f;

        const float4* xr[4];
        #pragma unroll
        for (int bi = 0; bi < 4; ++bi)
            xr[bi] = reinterpret_cast<const float4*>(x + ((size_t)(b0 + bi) * M_ + m) * D_);

        #pragma unroll 4
        for (int dq = 0; dq < 32; ++dq) {
            float4 wv[4];
            #pragma unroll
            for (int ti = 0; ti < 4; ++ti) wv[ti] = ws4[(tx + 16 * ti) * 33 + dq];
            #pragma unroll
            for (int bi = 0; bi < 4; ++bi) {
                float4 xv = __ldg(&xr[bi][dq]);
                #pragma unroll
                for (int ti = 0; ti < 4; ++ti) {
                    acc[bi][ti] = fmaf(xv.x, wv[ti].x, acc[bi][ti]);
                    acc[bi][ti] = fmaf(xv.y, wv[ti].y, acc[bi][ti]);
                    acc[bi][ti] = fmaf(xv.z, wv[ti].z, acc[bi][ti]);
                    acc[bi][ti] = fmaf(xv.w, wv[ti].w, acc[bi][ti]);
                }
            }
        }
        #pragma unroll
        for (int bi = 0; bi < 4; ++bi) {
            float* dst = g_priors + ((size_t)(n * B_ + b0 + bi) * M_ + m) * T_;
            #pragma unroll
            for (int ti = 0; ti < 4; ++ti) dst[tx + 16 * ti] = acc[bi][ti];
        }
    }
}

// ---------------------------------------------------------------------------
// K3: per (b,n) block (128 threads): votes GEMM + sigmoid, mean-over-M,
//     dispersion, relu, softmax over M, next_caps, layernorm.
//     Dynamic smem: lh[128][68] + ps[64][68] + vt[64][132] + small = 87296 B.
// ---------------------------------------------------------------------------
__global__ __launch_bounds__(128) void k_route(
    const float* __restrict__ thr, const float* __restrict__ gamma,
    const float* __restrict__ beta, float* __restrict__ out)
{
    extern __shared__ float smdyn[];
    float* lh   = smdyn;            // L_*68
    float* ps   = lh + L_ * 68;     // M_*68
    float* vt   = ps + M_ * 68;     // M_*132
    float* vbar = vt + M_ * 132;    // L_
    float* wgt  = vbar + L_;        // M_
    float* prob = wgt + M_;         // M_
    float* ncs  = prob + M_;        // T_

    int tid = threadIdx.x;
    int b = blockIdx.x & 255;       // B_ = 256
    int n = blockIdx.x >> 8;

    for (int i = tid; i < L_ * T_; i += 128) lh[(i >> 6) * 68 + (i & 63)] = g_lh[i];
    {
        const float* src = g_priors + ((size_t)(n * B_ + b) * M_) * T_;
        for (int i = tid; i < M_ * T_; i += 128) ps[(i >> 6) * 68 + (i & 63)] = src[i];
    }
    __syncthreads();

    const float4* lh4 = reinterpret_cast<const float4*>(lh);  // row stride 17 f4
    const float4* ps4 = reinterpret_cast<const float4*>(ps);
    int lx = tid & 15;              // l = lx + 16*j
    int my = tid >> 4;
    int m0 = my * 8;                // 8 m's per thread

    #pragma unroll 1
    for (int p = 0; p < 2; ++p) {   // two l-half passes (32 accs each)
        float acc[8][4];
        #pragma unroll
        for (int i = 0; i < 8; ++i)
            #pragma unroll
            for (int j = 0; j < 4; ++j) acc[i][j] = 0.f;

        #pragma unroll 2
        for (int tq = 0; tq < 16; ++tq) {
            float4 hv[4];
            #pragma unroll
            for (int j = 0; j < 4; ++j) hv[j] = lh4[(lx + 16 * (p * 4 + j)) * 17 + tq];
            #pragma unroll
            for (int i = 0; i < 8; ++i) {
                float4 pv = ps4[(m0 + i) * 17 + tq];
                #pragma unroll
                for (int j = 0; j < 4; ++j) {
                    acc[i][j] = fmaf(pv.x, hv[j].x, acc[i][j]);
                    acc[i][j] = fmaf(pv.y, hv[j].y, acc[i][j]);
                    acc[i][j] = fmaf(pv.z, hv[j].z, acc[i][j]);
                    acc[i][j] = fmaf(pv.w, hv[j].w, acc[i][j]);
                }
            }
        }
        #pragma unroll
        for (int i = 0; i < 8; ++i)
            #pragma unroll
            for (int j = 0; j < 4; ++j) {
                float v = 1.0f / (1.0f + __expf(-acc[i][j]));  // sigmoid
                vt[(m0 + i) * 132 + lx + 16 * (p * 4 + j)] = v;
            }
    }
    __syncthreads();

    // mean over M per l
    {
        float s = 0.f;
        #pragma unroll 8
        for (int m = 0; m < M_; ++m) s += vt[m * 132 + tid];
        vbar[tid] = s * (1.0f / M_);
    }
    __syncthreads();

    // dispersion + relu(thread^2 - dis): 2 threads per m
    {
        int m = tid >> 1, h = tid & 1;
        float s = 0.f;
        #pragma unroll 8
        for (int j = 0; j < 64; ++j) {
            int l = (h << 6) + j;
            float dv = vt[m * 132 + l] - vbar[l];
            s = fmaf(dv, dv, s);
        }
        s += __shfl_xor_sync(0xffffffffu, s, 1);
        if (h == 0) {
            float tw = thr[m * N_ + n];
            wgt[m] = fmaxf(fmaf(tw, tw, -s * (1.0f / L_)), 0.0f);
        }
    }
    __syncthreads();

    // softmax over M (redundant serial scans, cheap)
    float mxw = -3.0e38f;
    #pragma unroll 8
    for (int m = 0; m < M_; ++m) mxw = fmaxf(mxw, wgt[m]);
    if (tid < M_) prob[tid] = __expf(wgt[tid] - mxw);
    __syncthreads();
    float psum = 0.f;
    #pragma unroll 8
    for (int m = 0; m < M_; ++m) psum += prob[m];

    // next_caps
    if (tid < T_) {
        float nc = 0.f;
        #pragma unroll 8
        for (int m = 0; m < M_; ++m) nc = fmaf(prob[m], ps[m * 68 + tid], nc);
        ncs[tid] = nc / psum;
    }
    __syncthreads();

    // layernorm over T
    if (tid < T_) {
        float mu = 0.f;
        #pragma unroll 8
        for (int t2 = 0; t2 < T_; ++t2) mu += ncs[t2];
        mu *= (1.0f / T_);
        float var = 0.f;
        #pragma unroll 8
        for (int t2 = 0; t2 < T_; ++t2) { float dv = ncs[t2] - mu; var = fmaf(dv, dv, var); }
        var *= (1.0f / T_);
        float y = (ncs[tid] - mu) * rsqrtf(var + 1e-5f) * gamma[tid] + beta[tid];
        out[((size_t)b * N_ + n) * T_ + tid] = y;
    }
}

// ---------------------------------------------------------------------------
// Launch: x, route_weights, thread, routing_leaves, ln_gamma, ln_beta -> out [B,N,T]
// ---------------------------------------------------------------------------
extern "C" void kernel_launch(void* const* d_in, const int* in_sizes, int n_in,
                              void* d_out, int out_size) {
    const float* x      = (const float*)d_in[0];
    const float* rw     = (const float*)d_in[1];
    const float* thr    = (const float*)d_in[2];
    const float* leaves = (const float*)d_in[3];
    const float* gamma  = (const float*)d_in[4];
    const float* beta   = (const float*)d_in[5];
    float* out = (float*)d_out;

    k_leaves<<<1, 128>>>(leaves);
    k_entmax<<<M_ * N_, 64>>>(rw);
    k_priors<<<M_ * N_, 256>>>(x);

    const int smem_route = (L_ * 68 + M_ * 68 + M_ * 132 + L_ + M_ + M_ + T_) * 4;  // 87296 B
    cudaFuncSetAttribute(k_route, cudaFuncAttributeMaxDynamicSharedMemorySize, smem_route);
    k_route<<<B_ * N_, 128, smem_route>>>(thr, gamma, beta, out);
}

// round 2
// speedup vs baseline: 1.2251x; 1.2251x over previous
#include <cuda_runtime.h>
#include <math.h>

#define B_ 256
#define M_ 64
#define N_ 32
#define D_ 128
#define T_ 64
#define L_ 128

// Scratch (allocation-free: __device__ globals)
__device__ float g_WT[(size_t)M_ * N_ * D_ * T_];      // entmax weights, [mn][d][t]
__device__ float g_priors[(size_t)N_ * B_ * M_ * T_];  // priors, [n][b][m][t]
__device__ float g_lh[L_ * T_];                        // normalized leaves

// ---------------------------------------------------------------------------
// K0: normalize routing_leaves rows
// ---------------------------------------------------------------------------
__global__ void k_leaves(const float* __restrict__ leaves) {
    int l = threadIdx.x;
    if (l < L_) {
        float s = 0.f;
        #pragma unroll
        for (int t = 0; t < T_; ++t) { float v = leaves[l * T_ + t]; s = fmaf(v, v, s); }
        float inv = 1.0f / fmaxf(sqrtf(s), 1e-12f);
        #pragma unroll
        for (int t = 0; t < T_; ++t) g_lh[l * T_ + t] = leaves[l * T_ + t] * inv;
    }
}

// ---------------------------------------------------------------------------
// K1: exact 1.5-entmax over D per (m,n,t) column. tau solves
//     f(tau) = sum max(z - tau, 0)^2 = 1 on [-1, 0] (z shifted so z_max = 0).
//     12 bisection + 2 Newton (f convex decreasing -> Newton is safe/monotone).
//     2 threads per column (64 z-regs each), shfl_xor(1) partial reduce.
//     Output layout: g_WT[mn][d][t].
// ---------------------------------------------------------------------------
__global__ __launch_bounds__(128) void k_entmax(const float* __restrict__ rw) {
    __shared__ float sm[D_ * 65];  // [d][t] pad 65
    int mn = blockIdx.x;
    const float* src = rw + (size_t)mn * D_ * T_;
    for (int i = threadIdx.x; i < D_ * T_; i += 128)
        sm[(i >> 6) * 65 + (i & 63)] = src[i];
    __syncthreads();

    int col = threadIdx.x >> 1, half = threadIdx.x & 1;
    float z[64];
    float mx = -3.0e38f;
    #pragma unroll
    for (int k = 0; k < 64; ++k) {
        z[k] = sm[(half * 64 + k) * 65 + col];
        mx = fmaxf(mx, z[k]);
    }
    mx = fmaxf(mx, __shfl_xor_sync(0xffffffffu, mx, 1));
    #pragma unroll
    for (int k = 0; k < 64; ++k) z[k] = 0.5f * z[k] - 0.5f * mx;

    float lo = -1.0f, hi = 0.0f;
    #pragma unroll 1
    for (int it = 0; it < 12; ++it) {
        float mid = 0.5f * (lo + hi);
        float s0 = 0.f, s1 = 0.f, s2 = 0.f, s3 = 0.f;
        #pragma unroll
        for (int k = 0; k < 64; k += 4) {
            float a0 = fmaxf(z[k + 0] - mid, 0.f); s0 = fmaf(a0, a0, s0);
            float a1 = fmaxf(z[k + 1] - mid, 0.f); s1 = fmaf(a1, a1, s1);
            float a2 = fmaxf(z[k + 2] - mid, 0.f); s2 = fmaf(a2, a2, s2);
            float a3 = fmaxf(z[k + 3] - mid, 0.f); s3 = fmaf(a3, a3, s3);
        }
        float s = (s0 + s1) + (s2 + s3);
        s += __shfl_xor_sync(0xffffffffu, s, 1);
        if (s >= 1.0f) lo = mid; else hi = mid;
    }
    float tau = 0.5f * (lo + hi);
    #pragma unroll 1
    for (int it = 0; it < 2; ++it) {
        float f0 = 0.f, f1 = 0.f, g0 = 0.f, g1 = 0.f;
        #pragma unroll
        for (int k = 0; k < 64; k += 2) {
            float a0 = fmaxf(z[k + 0] - tau, 0.f); f0 = fmaf(a0, a0, f0); g0 += a0;
            float a1 = fmaxf(z[k + 1] - tau, 0.f); f1 = fmaf(a1, a1, f1); g1 += a1;
        }
        float f = f0 + f1, g = g0 + g1;
        f += __shfl_xor_sync(0xffffffffu, f, 1);
        g += __shfl_xor_sync(0xffffffffu, g, 1);
        tau += (f - 1.0f) / fmaxf(2.0f * g, 1e-12f);
    }

    #pragma unroll
    for (int k = 0; k < 64; ++k) {
        float a = fmaxf(z[k] - tau, 0.f);
        sm[(half * 64 + k) * 65 + col] = a * a;
    }
    __syncthreads();
    float* dst = g_WT + (size_t)mn * D_ * T_;  // [d][t]
    for (int i = threadIdx.x; i < D_ * T_; i += 128)
        dst[i] = sm[(i >> 6) * 65 + (i & 63)];
}

// ---------------------------------------------------------------------------
// K2: priors[b,m,n,t] = sum_d x[b,m,d] * W[m,n,d,t].
//     One block per (m,n): GEMM [256 b x 64 t], K = 128.
//     W staged [d][t] stride 68 -> ld.shared.v2.b64 gives packed (t0,t1),(t2,t3).
//     Packed fma.rn.f32x2: thread tile 4 b x 4 t (t = tx*4..+3).
//     Output [n][b][m][t].
// ---------------------------------------------------------------------------
__global__ __launch_bounds__(256) void k_priors(const float* __restrict__ x) {
    __shared__ __align__(16) float ws[D_ * 68];
    int mn = blockIdx.x;
    int m = mn >> 5, n = mn & 31;
    {
        const float* wsrc = g_WT + (size_t)mn * D_ * T_;  // [d][t]
        for (int i = threadIdx.x; i < D_ * T_; i += 256)
            ws[(i >> 6) * 68 + (i & 63)] = wsrc[i];
    }
    __syncthreads();
    unsigned wsb = (unsigned)__cvta_generic_to_shared(ws);
    int tx = threadIdx.x & 15;   // t-quad: t = tx*4..tx*4+3
    int ty = threadIdx.x >> 4;   // b-group
    unsigned wcol = wsb + (unsigned)tx * 16u;

    #pragma unroll 1
    for (int chunk = 0; chunk < 4; ++chunk) {
        int b0 = chunk * 64 + ty * 4;
        unsigned long long acc[4][2];
        #pragma unroll
        for (int bi = 0; bi < 4; ++bi) { acc[bi][0] = 0ull; acc[bi][1] = 0ull; }

        const float4* xr[4];
        #pragma unroll
        for (int bi = 0; bi < 4; ++bi)
            xr[bi] = reinterpret_cast<const float4*>(x + ((size_t)(b0 + bi) * M_ + m) * D_);

        #pragma unroll 2
        for (int dq = 0; dq < 32; ++dq) {
            float4 xv[4];
            #pragma unroll
            for (int bi = 0; bi < 4; ++bi) xv[bi] = __ldg(&xr[bi][dq]);
            #pragma unroll
            for (int dd = 0; dd < 4; ++dd) {
                unsigned long long w01, w23;
                unsigned addr = wcol + (unsigned)(dq * 4 + dd) * 272u;  // 68 floats
                asm volatile("ld.shared.v2.b64 {%0,%1},[%2];"
                             : "=l"(w01), "=l"(w23) : "r"(addr));
                #pragma unroll
                for (int bi = 0; bi < 4; ++bi) {
                    float xs = (dd == 0) ? xv[bi].x : (dd == 1) ? xv[bi].y
                             : (dd == 2) ? xv[bi].z : xv[bi].w;
                    unsigned long long xb;
                    asm("mov.b64 %0, {%1,%1};" : "=l"(xb) : "f"(xs));
                    asm("fma.rn.f32x2 %0, %1, %2, %0;" : "+l"(acc[bi][0]) : "l"(xb), "l"(w01));
                    asm("fma.rn.f32x2 %0, %1, %2, %0;" : "+l"(acc[bi][1]) : "l"(xb), "l"(w23));
                }
            }
        }
        #pragma unroll
        for (int bi = 0; bi < 4; ++bi) {
            float4 o;
            asm("mov.b64 {%0,%1}, %2;" : "=f"(o.x), "=f"(o.y) : "l"(acc[bi][0]));
            asm("mov.b64 {%0,%1}, %2;" : "=f"(o.z), "=f"(o.w) : "l"(acc[bi][1]));
            *reinterpret_cast<float4*>(
                g_priors + ((size_t)(n * B_ + b0 + bi) * M_ + m) * T_ + tx * 4) = o;
        }
    }
}

// ---------------------------------------------------------------------------
// K3: per (b,n) block (256 threads): votes GEMM + sigmoid, mean-over-M,
//     dispersion, relu, softmax over M, next_caps, layernorm.
//     Votes are stored into the DEAD half of the lh smem region after each
//     GEMM pass (pass p only reads lh rows [64p, 64p+64)).
//     Dynamic smem: lh/votes 128*68 + ps 64*68 + 128+64*3 = 53504 B -> 4 blocks/SM.
// ---------------------------------------------------------------------------
__global__ __launch_bounds__(256, 4) void k_route(
    const float* __restrict__ thr, const float* __restrict__ gamma,
    const float* __restrict__ beta, float* __restrict__ out)
{
    extern __shared__ float smd[];
    float* lh   = smd;              // [128][68]; votes alias after each pass
    float* ps   = lh + L_ * 68;     // [64][68]
    float* vbar = ps + M_ * 68;     // 128
    float* wgt  = vbar + L_;        // 64
    float* prob = wgt + M_;         // 64
    float* ncs  = prob + M_;        // 64

    int tid = threadIdx.x;
    int b = blockIdx.x & 255;       // B_ = 256
    int n = blockIdx.x >> 8;

    for (int i = tid; i < L_ * T_; i += 256) lh[(i >> 6) * 68 + (i & 63)] = g_lh[i];
    {
        const float* src = g_priors + ((size_t)(n * B_ + b) * M_) * T_;
        for (int i = tid; i < M_ * T_; i += 256) ps[(i >> 6) * 68 + (i & 63)] = src[i];
    }
    __syncthreads();

    const float4* lh4 = reinterpret_cast<const float4*>(lh);  // row stride 17 f4
    const float4* ps4 = reinterpret_cast<const float4*>(ps);
    int lx = tid & 15;              // l = lx + 16*(4p+jj)
    int my = tid >> 4;              // m = 4*my + i

    #pragma unroll 1
    for (int p = 0; p < 2; ++p) {
        float acc[4][4];            // [i(m)][jj(l)]
        #pragma unroll
        for (int i = 0; i < 4; ++i)
            #pragma unroll
            for (int j = 0; j < 4; ++j) acc[i][j] = 0.f;

        #pragma unroll 2
        for (int tq = 0; tq < 16; ++tq) {
            float4 hv[4];
            #pragma unroll
            for (int j = 0; j < 4; ++j) hv[j] = lh4[(lx + 16 * (4 * p + j)) * 17 + tq];
            #pragma unroll
            for (int i = 0; i < 4; ++i) {
                float4 pv = ps4[(4 * my + i) * 17 + tq];
                #pragma unroll
                for (int j = 0; j < 4; ++j) {
                    acc[i][j] = fmaf(pv.x, hv[j].x, acc[i][j]);
                    acc[i][j] = fmaf(pv.y, hv[j].y, acc[i][j]);
                    acc[i][j] = fmaf(pv.z, hv[j].z, acc[i][j]);
                    acc[i][j] = fmaf(pv.w, hv[j].w, acc[i][j]);
                }
            }
        }
        __syncthreads();  // all reads of lh rows [64p,64p+64) done -> region dead
        // sigmoid + store votes into the dead lh half: v(m,l) at
        // lh[ ((l & 64) + m) * 68 + (l & 63) ]
        #pragma unroll
        for (int i = 0; i < 4; ++i)
            #pragma unroll
            for (int j = 0; j < 4; ++j) {
                float v = 1.0f / (1.0f + __expf(-acc[i][j]));
                int l = lx + 16 * (4 * p + j);
                lh[((l & 64) + 4 * my + i) * 68 + (l & 63)] = v;
            }
        // no sync needed before p=1 GEMM: it reads lh rows 64..127 (untouched)
    }
    __syncthreads();

    // vbar[l] = mean over m
    if (tid < L_) {
        int base = (tid & 64) * 68 + (tid & 63);
        float s = 0.f;
        #pragma unroll 8
        for (int m = 0; m < M_; ++m) s += lh[base + m * 68];
        vbar[tid] = s * (1.0f / M_);
    }
    __syncthreads();

    // dispersion + relu(thread^2 - dis): 4 threads per m
    {
        int m = tid >> 2, q = tid & 3;
        float s = 0.f;
        #pragma unroll 8
        for (int k = 0; k < 32; ++k) {
            int l = q * 32 + k;
            float dv = lh[((l & 64) + m) * 68 + (l & 63)] - vbar[l];
            s = fmaf(dv, dv, s);
        }
        s += __shfl_xor_sync(0xffffffffu, s, 1);
        s += __shfl_xor_sync(0xffffffffu, s, 2);
        if (q == 0) {
            float tw = thr[m * N_ + n];
            wgt[m] = fmaxf(fmaf(tw, tw, -s * (1.0f / L_)), 0.0f);
        }
    }
    __syncthreads();

    // softmax over M
    if (tid < M_) {
        float mxw = -3.0e38f;
        #pragma unroll 8
        for (int m = 0; m < M_; ++m) mxw = fmaxf(mxw, wgt[m]);
        prob[tid] = __expf(wgt[tid] - mxw);
    }
    __syncthreads();

    // next_caps
    if (tid < T_) {
        float psum = 0.f;
        #pragma unroll 8
        for (int m = 0; m < M_; ++m) psum += prob[m];
        float nc = 0.f;
        #pragma unroll 8
        for (int m = 0; m < M_; ++m) nc = fmaf(prob[m], ps[m * 68 + tid], nc);
        ncs[tid] = nc / psum;
    }
    __syncthreads();

    // layernorm over T
    if (tid < T_) {
        float mu = 0.f;
        #pragma unroll 8
        for (int t2 = 0; t2 < T_; ++t2) mu += ncs[t2];
        mu *= (1.0f / T_);
        float var = 0.f;
        #pragma unroll 8
        for (int t2 = 0; t2 < T_; ++t2) { float dv = ncs[t2] - mu; var = fmaf(dv, dv, var); }
        var *= (1.0f / T_);
        float y = (ncs[tid] - mu) * rsqrtf(var + 1e-5f) * gamma[tid] + beta[tid];
        out[((size_t)b * N_ + n) * T_ + tid] = y;
    }
}

// ---------------------------------------------------------------------------
// Launch
// ---------------------------------------------------------------------------
extern "C" void kernel_launch(void* const* d_in, const int* in_sizes, int n_in,
                              void* d_out, int out_size) {
    const float* x      = (const float*)d_in[0];
    const float* rw     = (const float*)d_in[1];
    const float* thr    = (const float*)d_in[2];
    const float* leaves = (const float*)d_in[3];
    const float* gamma  = (const float*)d_in[4];
    const float* beta   = (const float*)d_in[5];
    float* out = (float*)d_out;

    k_leaves<<<1, 128>>>(leaves);
    k_entmax<<<M_ * N_, 128>>>(rw);
    k_priors<<<M_ * N_, 256>>>(x);

    const int smem_route = (L_ * 68 + M_ * 68 + L_ + 3 * M_) * 4;  // 53504 B
    static int attr_set = 0;
    if (!attr_set) {
        cudaFuncSetAttribute(k_route, cudaFuncAttributeMaxDynamicSharedMemorySize, smem_route);
        attr_set = 1;
    }
    k_route<<<B_ * N_, 256, smem_route>>>(thr, gamma, beta, out);
}

// round 3
// speedup vs baseline: 1.2605x; 1.0290x over previous
#include <cuda_runtime.h>
#include <math.h>

#define B_ 256
#define M_ 64
#define N_ 32
#define D_ 128
#define T_ 64
#define L_ 128

// Scratch (allocation-free: __device__ globals)
__device__ float g_WT[(size_t)M_ * N_ * D_ * T_];      // entmax weights, [mn][d][t]
__device__ float g_priors[(size_t)N_ * B_ * M_ * T_];  // priors, [n][b][m][t]
__device__ float g_lh[T_ * L_];                        // normalized leaves, TRANSPOSED [t][l]

// ---------------------------------------------------------------------------
// K0: normalize routing_leaves rows; store transposed [t][l]
// ---------------------------------------------------------------------------
__global__ void k_leaves(const float* __restrict__ leaves) {
    int l = threadIdx.x;
    if (l < L_) {
        float s = 0.f;
        #pragma unroll
        for (int t = 0; t < T_; ++t) { float v = leaves[l * T_ + t]; s = fmaf(v, v, s); }
        float inv = 1.0f / fmaxf(sqrtf(s), 1e-12f);
        #pragma unroll
        for (int t = 0; t < T_; ++t) g_lh[t * L_ + l] = leaves[l * T_ + t] * inv;
    }
}

// ---------------------------------------------------------------------------
// K1: exact 1.5-entmax over D per (m,n,t) column. tau solves
//     f(tau) = sum max(z - tau, 0)^2 = 1 on [-1, 0] (z shifted so z_max = 0).
//     12 bisection + 2 Newton. 2 threads per column, shfl_xor(1) reduce.
//     Output layout: g_WT[mn][d][t].
// ---------------------------------------------------------------------------
__global__ __launch_bounds__(128) void k_entmax(const float* __restrict__ rw) {
    __shared__ float sm[D_ * 65];  // [d][t] pad 65
    int mn = blockIdx.x;
    const float* src = rw + (size_t)mn * D_ * T_;
    for (int i = threadIdx.x; i < D_ * T_; i += 128)
        sm[(i >> 6) * 65 + (i & 63)] = src[i];
    __syncthreads();

    int col = threadIdx.x >> 1, half = threadIdx.x & 1;
    float z[64];
    float mx = -3.0e38f;
    #pragma unroll
    for (int k = 0; k < 64; ++k) {
        z[k] = sm[(half * 64 + k) * 65 + col];
        mx = fmaxf(mx, z[k]);
    }
    mx = fmaxf(mx, __shfl_xor_sync(0xffffffffu, mx, 1));
    #pragma unroll
    for (int k = 0; k < 64; ++k) z[k] = 0.5f * z[k] - 0.5f * mx;

    float lo = -1.0f, hi = 0.0f;
    #pragma unroll 1
    for (int it = 0; it < 12; ++it) {
        float mid = 0.5f * (lo + hi);
        float s0 = 0.f, s1 = 0.f, s2 = 0.f, s3 = 0.f;
        #pragma unroll
        for (int k = 0; k < 64; k += 4) {
            float a0 = fmaxf(z[k + 0] - mid, 0.f); s0 = fmaf(a0, a0, s0);
            float a1 = fmaxf(z[k + 1] - mid, 0.f); s1 = fmaf(a1, a1, s1);
            float a2 = fmaxf(z[k + 2] - mid, 0.f); s2 = fmaf(a2, a2, s2);
            float a3 = fmaxf(z[k + 3] - mid, 0.f); s3 = fmaf(a3, a3, s3);
        }
        float s = (s0 + s1) + (s2 + s3);
        s += __shfl_xor_sync(0xffffffffu, s, 1);
        if (s >= 1.0f) lo = mid; else hi = mid;
    }
    float tau = 0.5f * (lo + hi);
    #pragma unroll 1
    for (int it = 0; it < 2; ++it) {
        float f0 = 0.f, f1 = 0.f, g0 = 0.f, g1 = 0.f;
        #pragma unroll
        for (int k = 0; k < 64; k += 2) {
            float a0 = fmaxf(z[k + 0] - tau, 0.f); f0 = fmaf(a0, a0, f0); g0 += a0;
            float a1 = fmaxf(z[k + 1] - tau, 0.f); f1 = fmaf(a1, a1, f1); g1 += a1;
        }
        float f = f0 + f1, g = g0 + g1;
        f += __shfl_xor_sync(0xffffffffu, f, 1);
        g += __shfl_xor_sync(0xffffffffu, g, 1);
        tau += (f - 1.0f) / fmaxf(2.0f * g, 1e-12f);
    }

    #pragma unroll
    for (int k = 0; k < 64; ++k) {
        float a = fmaxf(z[k] - tau, 0.f);
        sm[(half * 64 + k) * 65 + col] = a * a;
    }
    __syncthreads();
    float* dst = g_WT + (size_t)mn * D_ * T_;  // [d][t]
    for (int i = threadIdx.x; i < D_ * T_; i += 128)
        dst[i] = sm[(i >> 6) * 65 + (i & 63)];
}

// ---------------------------------------------------------------------------
// K2: priors[b,m,n,t] = sum_d x[b,m,d] * W[m,n,d,t].
//     One block per (m,n): GEMM [256 b x 64 t], K = 128.
//     W staged [d][t] stride 68. Thread tile 4 b x 8 t, packed fma.rn.f32x2.
//     Output [n][b][m][t].
// ---------------------------------------------------------------------------
__global__ __launch_bounds__(256) void k_priors(const float* __restrict__ x) {
    __shared__ __align__(16) float ws[D_ * 68];
    int mn = blockIdx.x;
    int m = mn >> 5, n = mn & 31;
    {
        const float* wsrc = g_WT + (size_t)mn * D_ * T_;  // [d][t]
        for (int i = threadIdx.x; i < D_ * T_; i += 256)
            ws[(i >> 6) * 68 + (i & 63)] = wsrc[i];
    }
    __syncthreads();
    unsigned wsb = (unsigned)__cvta_generic_to_shared(ws);
    int tx = threadIdx.x & 7;    // t-oct: t = tx*8 .. +7
    int ty = threadIdx.x >> 3;   // b-group (0..31)
    unsigned wcol = wsb + (unsigned)tx * 32u;

    #pragma unroll 1
    for (int chunk = 0; chunk < 2; ++chunk) {
        int b0 = chunk * 128 + ty * 4;
        unsigned long long acc[4][4];
        #pragma unroll
        for (int bi = 0; bi < 4; ++bi)
            #pragma unroll
            for (int j = 0; j < 4; ++j) acc[bi][j] = 0ull;

        const float4* xr[4];
        #pragma unroll
        for (int bi = 0; bi < 4; ++bi)
            xr[bi] = reinterpret_cast<const float4*>(x + ((size_t)(b0 + bi) * M_ + m) * D_);

        #pragma unroll 2
        for (int dq = 0; dq < 32; ++dq) {
            float4 xv[4];
            #pragma unroll
            for (int bi = 0; bi < 4; ++bi) xv[bi] = __ldg(&xr[bi][dq]);
            #pragma unroll
            for (int dd = 0; dd < 4; ++dd) {
                unsigned long long w01, w23, w45, w67;
                unsigned a = wcol + (unsigned)(dq * 4 + dd) * 272u;
                asm volatile("ld.shared.v2.b64 {%0,%1},[%2];" : "=l"(w01), "=l"(w23) : "r"(a));
                asm volatile("ld.shared.v2.b64 {%0,%1},[%2];" : "=l"(w45), "=l"(w67) : "r"(a + 16u));
                #pragma unroll
                for (int bi = 0; bi < 4; ++bi) {
                    float xs = (dd == 0) ? xv[bi].x : (dd == 1) ? xv[bi].y
                             : (dd == 2) ? xv[bi].z : xv[bi].w;
                    unsigned long long xb;
                    asm("mov.b64 %0, {%1,%1};" : "=l"(xb) : "f"(xs));
                    asm("fma.rn.f32x2 %0, %1, %2, %0;" : "+l"(acc[bi][0]) : "l"(xb), "l"(w01));
                    asm("fma.rn.f32x2 %0, %1, %2, %0;" : "+l"(acc[bi][1]) : "l"(xb), "l"(w23));
                    asm("fma.rn.f32x2 %0, %1, %2, %0;" : "+l"(acc[bi][2]) : "l"(xb), "l"(w45));
                    asm("fma.rn.f32x2 %0, %1, %2, %0;" : "+l"(acc[bi][3]) : "l"(xb), "l"(w67));
                }
            }
        }
        #pragma unroll
        for (int bi = 0; bi < 4; ++bi) {
            float4 o0, o1;
            asm("mov.b64 {%0,%1}, %2;" : "=f"(o0.x), "=f"(o0.y) : "l"(acc[bi][0]));
            asm("mov.b64 {%0,%1}, %2;" : "=f"(o0.z), "=f"(o0.w) : "l"(acc[bi][1]));
            asm("mov.b64 {%0,%1}, %2;" : "=f"(o1.x), "=f"(o1.y) : "l"(acc[bi][2]));
            asm("mov.b64 {%0,%1}, %2;" : "=f"(o1.z), "=f"(o1.w) : "l"(acc[bi][3]));
            float* dst = g_priors + ((size_t)(n * B_ + b0 + bi) * M_ + m) * T_ + tx * 8;
            *reinterpret_cast<float4*>(dst) = o0;
            *reinterpret_cast<float4*>(dst + 4) = o1;
        }
    }
}

// ---------------------------------------------------------------------------
// K3: per (b,n) block (128 threads): votes GEMM (8m x 8l f32x2 tiles) +
//     sigmoid, mean-over-M, dispersion, relu, softmax over M, next_caps, LN.
//     lh staged transposed [t][l] (stride 136); votes overwrite it after GEMM.
//     Dynamic smem 53504 B -> 4 blocks/SM.
// ---------------------------------------------------------------------------
__global__ __launch_bounds__(128) void k_route(
    const float* __restrict__ thr, const float* __restrict__ gamma,
    const float* __restrict__ beta, float* __restrict__ out)
{
    extern __shared__ float smd[];
    float* lhT  = smd;                 // [64 t][136]; votes [64 m][132] alias after GEMM
    float* ps   = lhT + T_ * 136;      // [64 m][68]
    float* vbar = ps + M_ * 68;        // 128
    float* wgt  = vbar + L_;           // 64
    float* prob = wgt + M_;            // 64
    float* ncs  = prob + M_;           // 64

    int tid = threadIdx.x;
    int b = blockIdx.x & 255;          // B_ = 256
    int n = blockIdx.x >> 8;

    for (int i = tid; i < T_ * L_; i += 128) lhT[(i >> 7) * 136 + (i & 127)] = g_lh[i];
    {
        const float* src = g_priors + ((size_t)(n * B_ + b) * M_) * T_;
        for (int i = tid; i < M_ * T_; i += 128) ps[(i >> 6) * 68 + (i & 63)] = src[i];
    }
    __syncthreads();

    unsigned lhb = (unsigned)__cvta_generic_to_shared(lhT);
    unsigned psb = lhb + (unsigned)(T_ * 136 * 4);
    int lx = tid & 15;                 // l = lx*8 .. +7
    int my = tid >> 4;                 // m = my*8 .. +7
    unsigned hrow = lhb + (unsigned)lx * 32u;
    unsigned prow = psb + (unsigned)my * 2176u;  // my*8 rows * 272B

    unsigned long long acc[8][4];
    #pragma unroll
    for (int i = 0; i < 8; ++i)
        #pragma unroll
        for (int j = 0; j < 4; ++j) acc[i][j] = 0ull;

    #pragma unroll 2
    for (int tp = 0; tp < 32; ++tp) {  // t = 2tp, 2tp+1
        float2 pv[8];
        #pragma unroll
        for (int i = 0; i < 8; ++i)
            asm volatile("ld.shared.v2.f32 {%0,%1},[%2];"
                         : "=f"(pv[i].x), "=f"(pv[i].y)
                         : "r"(prow + (unsigned)i * 272u + (unsigned)tp * 8u));
        unsigned long long h0[4], h1[4];
        {
            unsigned a0 = hrow + (unsigned)(2 * tp) * 544u;
            asm volatile("ld.shared.v2.b64 {%0,%1},[%2];" : "=l"(h0[0]), "=l"(h0[1]) : "r"(a0));
            asm volatile("ld.shared.v2.b64 {%0,%1},[%2];" : "=l"(h0[2]), "=l"(h0[3]) : "r"(a0 + 16u));
            asm volatile("ld.shared.v2.b64 {%0,%1},[%2];" : "=l"(h1[0]), "=l"(h1[1]) : "r"(a0 + 544u));
            asm volatile("ld.shared.v2.b64 {%0,%1},[%2];" : "=l"(h1[2]), "=l"(h1[3]) : "r"(a0 + 560u));
        }
        #pragma unroll
        for (int i = 0; i < 8; ++i) {
            unsigned long long pa, pb;
            asm("mov.b64 %0, {%1,%1};" : "=l"(pa) : "f"(pv[i].x));
            asm("fma.rn.f32x2 %0, %1, %2, %0;" : "+l"(acc[i][0]) : "l"(pa), "l"(h0[0]));
            asm("fma.rn.f32x2 %0, %1, %2, %0;" : "+l"(acc[i][1]) : "l"(pa), "l"(h0[1]));
            asm("fma.rn.f32x2 %0, %1, %2, %0;" : "+l"(acc[i][2]) : "l"(pa), "l"(h0[2]));
            asm("fma.rn.f32x2 %0, %1, %2, %0;" : "+l"(acc[i][3]) : "l"(pa), "l"(h0[3]));
            asm("mov.b64 %0, {%1,%1};" : "=l"(pb) : "f"(pv[i].y));
            asm("fma.rn.f32x2 %0, %1, %2, %0;" : "+l"(acc[i][0]) : "l"(pb), "l"(h1[0]));
            asm("fma.rn.f32x2 %0, %1, %2, %0;" : "+l"(acc[i][1]) : "l"(pb), "l"(h1[1]));
            asm("fma.rn.f32x2 %0, %1, %2, %0;" : "+l"(acc[i][2]) : "l"(pb), "l"(h1[2]));
            asm("fma.rn.f32x2 %0, %1, %2, %0;" : "+l"(acc[i][3]) : "l"(pb), "l"(h1[3]));
        }
    }
    __syncthreads();  // all lhT reads done -> region dead, reuse as votes [m][132]

    // sigmoid + store votes
    #pragma unroll
    for (int i = 0; i < 8; ++i) {
        unsigned vrow = lhb + (unsigned)((my * 8 + i) * 132 + lx * 8) * 4u;
        #pragma unroll
        for (int j = 0; j < 4; ++j) {
            float v0, v1;
            asm("mov.b64 {%0,%1}, %2;" : "=f"(v0), "=f"(v1) : "l"(acc[i][j]));
            v0 = 1.0f / (1.0f + __expf(-v0));
            v1 = 1.0f / (1.0f + __expf(-v1));
            asm volatile("st.shared.v2.f32 [%0],{%1,%2};"
                         :: "r"(vrow + (unsigned)j * 8u), "f"(v0), "f"(v1) : "memory");
        }
    }
    __syncthreads();
    float* vt = lhT;  // [m][132]

    // vbar[l] = mean over m
    {
        float s = 0.f;
        #pragma unroll 8
        for (int m = 0; m < M_; ++m) s += vt[m * 132 + tid];
        vbar[tid] = s * (1.0f / M_);
    }
    __syncthreads();

    // dispersion + relu(thread^2 - dis): 2 threads per m
    {
        int m = tid >> 1, h = tid & 1;
        float s = 0.f;
        #pragma unroll 8
        for (int k = 0; k < 64; ++k) {
            int l = h * 64 + k;
            float dv = vt[m * 132 + l] - vbar[l];
            s = fmaf(dv, dv, s);
        }
        s += __shfl_xor_sync(0xffffffffu, s, 1);
        if (h == 0) {
            float tw = thr[m * N_ + n];
            wgt[m] = fmaxf(fmaf(tw, tw, -s * (1.0f / L_)), 0.0f);
        }
    }
    __syncthreads();

    // softmax over M
    if (tid < M_) {
        float mxw = -3.0e38f;
        #pragma unroll 8
        for (int m = 0; m < M_; ++m) mxw = fmaxf(mxw, wgt[m]);
        prob[tid] = __expf(wgt[tid] - mxw);
    }
    __syncthreads();

    // next_caps
    if (tid < T_) {
        float psum = 0.f;
        #pragma unroll 8
        for (int m = 0; m < M_; ++m) psum += prob[m];
        float nc = 0.f;
        #pragma unroll 8
        for (int m = 0; m < M_; ++m) nc = fmaf(prob[m], ps[m * 68 + tid], nc);
        ncs[tid] = nc / psum;
    }
    __syncthreads();

    // layernorm over T
    if (tid < T_) {
        float mu = 0.f;
        #pragma unroll 8
        for (int t2 = 0; t2 < T_; ++t2) mu += ncs[t2];
        mu *= (1.0f / T_);
        float var = 0.f;
        #pragma unroll 8
        for (int t2 = 0; t2 < T_; ++t2) { float dv = ncs[t2] - mu; var = fmaf(dv, dv, var); }
        var *= (1.0f / T_);
        float y = (ncs[tid] - mu) * rsqrtf(var + 1e-5f) * gamma[tid] + beta[tid];
        out[((size_t)b * N_ + n) * T_ + tid] = y;
    }
}

// ---------------------------------------------------------------------------
// Launch
// ---------------------------------------------------------------------------
extern "C" void kernel_launch(void* const* d_in, const int* in_sizes, int n_in,
                              void* d_out, int out_size) {
    const float* x      = (const float*)d_in[0];
    const float* rw     = (const float*)d_in[1];
    const float* thr    = (const float*)d_in[2];
    const float* leaves = (const float*)d_in[3];
    const float* gamma  = (const float*)d_in[4];
    const float* beta   = (const float*)d_in[5];
    float* out = (float*)d_out;

    k_leaves<<<1, 128>>>(leaves);
    k_entmax<<<M_ * N_, 128>>>(rw);
    k_priors<<<M_ * N_, 256>>>(x);

    const int smem_route = (T_ * 136 + M_ * 68 + L_ + 3 * M_) * 4;  // 53504 B
    static int attr_set = 0;
    if (!attr_set) {
        cudaFuncSetAttribute(k_route, cudaFuncAttributeMaxDynamicSharedMemorySize, smem_route);
        attr_set = 1;
    }
    k_route<<<B_ * N_, 128, smem_route>>>(thr, gamma, beta, out);
}

// round 7
// speedup vs baseline: 1.5899x; 1.2613x over previous
#include <cuda_runtime.h>
#include <math.h>

#define B_ 256
#define M_ 64
#define N_ 32
#define D_ 128
#define T_ 64
#define L_ 128

// Scratch (allocation-free: __device__ globals)
__device__ float g_WT[(size_t)M_ * N_ * D_ * T_];      // entmax weights, [mn][d][t]
__device__ float g_priors[(size_t)N_ * B_ * M_ * T_];  // priors, [n][b][m][t]
__device__ float g_lh[T_ * L_];                        // normalized leaves, TRANSPOSED [t][l]

// ---------------------------------------------------------------------------
// K0: normalize routing_leaves rows; store transposed [t][l]
// ---------------------------------------------------------------------------
__global__ void k_leaves(const float* __restrict__ leaves) {
    int l = threadIdx.x;
    if (l < L_) {
        float s = 0.f;
        #pragma unroll
        for (int t = 0; t < T_; ++t) { float v = leaves[l * T_ + t]; s = fmaf(v, v, s); }
        float inv = 1.0f / fmaxf(sqrtf(s), 1e-12f);
        #pragma unroll
        for (int t = 0; t < T_; ++t) g_lh[t * L_ + l] = leaves[l * T_ + t] * inv;
    }
}

// ---------------------------------------------------------------------------
// K1: exact 1.5-entmax over D per (m,n,t) column. tau solves
//     f(tau) = sum max(z - tau, 0)^2 = 1 on [-1, 0] (z shifted so z_max = 0).
//     12 bisection + 2 Newton. 2 threads per column, shfl_xor(1) reduce.
//     Output layout: g_WT[mn][d][t].
// ---------------------------------------------------------------------------
__global__ __launch_bounds__(128) void k_entmax(const float* __restrict__ rw) {
    __shared__ float sm[D_ * 65];  // [d][t] pad 65
    int mn = blockIdx.x;
    const float* src = rw + (size_t)mn * D_ * T_;
    for (int i = threadIdx.x; i < D_ * T_; i += 128)
        sm[(i >> 6) * 65 + (i & 63)] = src[i];
    __syncthreads();

    int col = threadIdx.x >> 1, half = threadIdx.x & 1;
    float z[64];
    float mx = -3.0e38f;
    #pragma unroll
    for (int k = 0; k < 64; ++k) {
        z[k] = sm[(half * 64 + k) * 65 + col];
        mx = fmaxf(mx, z[k]);
    }
    mx = fmaxf(mx, __shfl_xor_sync(0xffffffffu, mx, 1));
    #pragma unroll
    for (int k = 0; k < 64; ++k) z[k] = 0.5f * z[k] - 0.5f * mx;

    float lo = -1.0f, hi = 0.0f;
    #pragma unroll 1
    for (int it = 0; it < 12; ++it) {
        float mid = 0.5f * (lo + hi);
        float s0 = 0.f, s1 = 0.f, s2 = 0.f, s3 = 0.f;
        #pragma unroll
        for (int k = 0; k < 64; k += 4) {
            float a0 = fmaxf(z[k + 0] - mid, 0.f); s0 = fmaf(a0, a0, s0);
            float a1 = fmaxf(z[k + 1] - mid, 0.f); s1 = fmaf(a1, a1, s1);
            float a2 = fmaxf(z[k + 2] - mid, 0.f); s2 = fmaf(a2, a2, s2);
            float a3 = fmaxf(z[k + 3] - mid, 0.f); s3 = fmaf(a3, a3, s3);
        }
        float s = (s0 + s1) + (s2 + s3);
        s += __shfl_xor_sync(0xffffffffu, s, 1);
        if (s >= 1.0f) lo = mid; else hi = mid;
    }
    float tau = 0.5f * (lo + hi);
    #pragma unroll 1
    for (int it = 0; it < 2; ++it) {
        float f0 = 0.f, f1 = 0.f, g0 = 0.f, g1 = 0.f;
        #pragma unroll
        for (int k = 0; k < 64; k += 2) {
            float a0 = fmaxf(z[k + 0] - tau, 0.f); f0 = fmaf(a0, a0, f0); g0 += a0;
            float a1 = fmaxf(z[k + 1] - tau, 0.f); f1 = fmaf(a1, a1, f1); g1 += a1;
        }
        float f = f0 + f1, g = g0 + g1;
        f += __shfl_xor_sync(0xffffffffu, f, 1);
        g += __shfl_xor_sync(0xffffffffu, g, 1);
        tau += (f - 1.0f) / fmaxf(2.0f * g, 1e-12f);
    }

    #pragma unroll
    for (int k = 0; k < 64; ++k) {
        float a = fmaxf(z[k] - tau, 0.f);
        sm[(half * 64 + k) * 65 + col] = a * a;
    }
    __syncthreads();
    float* dst = g_WT + (size_t)mn * D_ * T_;  // [d][t]
    for (int i = threadIdx.x; i < D_ * T_; i += 128)
        dst[i] = sm[(i >> 6) * 65 + (i & 63)];
}

// ---------------------------------------------------------------------------
// K2: priors[b,m,n,t] = sum_d x[b,m,d] * W[m,n,d,t].
//     One block per (m,n): GEMM [256 b x 64 t], K = 128.
//     W staged [d][64] (no pad). Thread tile 4 b x 8 t, the 8 t's split as
//     two contiguous quads t = 4*tx..+3 and 32+4*tx..+3 so every 16B shared
//     load and every 16B global store is lane-contiguous (conflict-free).
//     Packed fma.rn.f32x2 accumulators. Output [n][b][m][t].
// ---------------------------------------------------------------------------
__global__ __launch_bounds__(256) void k_priors(const float* __restrict__ x) {
    __shared__ __align__(16) float ws[D_ * 64];  // [d][t], rows 256B
    int mn = blockIdx.x;
    int m = mn >> 5, n = mn & 31;
    {
        const float* wsrc = g_WT + (size_t)mn * D_ * T_;  // [d][t] same layout
        for (int i = threadIdx.x; i < D_ * T_; i += 256) ws[i] = wsrc[i];
    }
    __syncthreads();
    unsigned wsb = (unsigned)__cvta_generic_to_shared(ws);
    int tx = threadIdx.x & 7;    // t quads: 4tx..+3 and 32+4tx..+3
    int ty = threadIdx.x >> 3;   // b-group (0..31)
    unsigned wA = wsb + (unsigned)tx * 16u;        // quad A
    unsigned wB = wA + 128u;                       // quad B (t+32)

    #pragma unroll 1
    for (int chunk = 0; chunk < 2; ++chunk) {
        int b0 = chunk * 128 + ty * 4;
        unsigned long long acc[4][4];
        #pragma unroll
        for (int bi = 0; bi < 4; ++bi)
            #pragma unroll
            for (int j = 0; j < 4; ++j) acc[bi][j] = 0ull;

        const float4* xr[4];
        #pragma unroll
        for (int bi = 0; bi < 4; ++bi)
            xr[bi] = reinterpret_cast<const float4*>(x + ((size_t)(b0 + bi) * M_ + m) * D_);

        #pragma unroll 2
        for (int dq = 0; dq < 32; ++dq) {
            float4 xv[4];
            #pragma unroll
            for (int bi = 0; bi < 4; ++bi) xv[bi] = __ldg(&xr[bi][dq]);
            #pragma unroll
            for (int dd = 0; dd < 4; ++dd) {
                unsigned long long a01, a23, b01, b23;
                unsigned rowoff = (unsigned)(dq * 4 + dd) * 256u;
                asm volatile("ld.shared.v2.b64 {%0,%1},[%2];" : "=l"(a01), "=l"(a23) : "r"(wA + rowoff));
                asm volatile("ld.shared.v2.b64 {%0,%1},[%2];" : "=l"(b01), "=l"(b23) : "r"(wB + rowoff));
                #pragma unroll
                for (int bi = 0; bi < 4; ++bi) {
                    float xs = (dd == 0) ? xv[bi].x : (dd == 1) ? xv[bi].y
                             : (dd == 2) ? xv[bi].z : xv[bi].w;
                    unsigned long long xb;
                    asm("mov.b64 %0, {%1,%1};" : "=l"(xb) : "f"(xs));
                    asm("fma.rn.f32x2 %0, %1, %2, %0;" : "+l"(acc[bi][0]) : "l"(xb), "l"(a01));
                    asm("fma.rn.f32x2 %0, %1, %2, %0;" : "+l"(acc[bi][1]) : "l"(xb), "l"(a23));
                    asm("fma.rn.f32x2 %0, %1, %2, %0;" : "+l"(acc[bi][2]) : "l"(xb), "l"(b01));
                    asm("fma.rn.f32x2 %0, %1, %2, %0;" : "+l"(acc[bi][3]) : "l"(xb), "l"(b23));
                }
            }
        }
        #pragma unroll
        for (int bi = 0; bi < 4; ++bi) {
            float4 o0, o1;
            asm("mov.b64 {%0,%1}, %2;" : "=f"(o0.x), "=f"(o0.y) : "l"(acc[bi][0]));
            asm("mov.b64 {%0,%1}, %2;" : "=f"(o0.z), "=f"(o0.w) : "l"(acc[bi][1]));
            asm("mov.b64 {%0,%1}, %2;" : "=f"(o1.x), "=f"(o1.y) : "l"(acc[bi][2]));
            asm("mov.b64 {%0,%1}, %2;" : "=f"(o1.z), "=f"(o1.w) : "l"(acc[bi][3]));
            float* dst = g_priors + ((size_t)(n * B_ + b0 + bi) * M_ + m) * T_;
            *reinterpret_cast<float4*>(dst + 4 * tx) = o0;
            *reinterpret_cast<float4*>(dst + 32 + 4 * tx) = o1;
        }
    }
}

// ---------------------------------------------------------------------------
// K3: per (b,n) block (128 threads): votes GEMM (8m x 8l f32x2 tiles) +
//     sigmoid, mean-over-M, dispersion, relu, softmax over M, next_caps, LN.
//     lh staged [t][128] (conflict-free: thread's 8 l's are two contiguous
//     quads l = 4*lx..+3 and 64+4*lx..+3); votes overwrite it (stride 132)
//     after the GEMM. Dynamic smem 52480 B -> 4 blocks/SM.
// ---------------------------------------------------------------------------
__global__ __launch_bounds__(128) void k_route(
    const float* __restrict__ thr, const float* __restrict__ gamma,
    const float* __restrict__ beta, float* __restrict__ out)
{
    extern __shared__ float smd[];
    float* lhT  = smd;                 // GEMM: [64 t][128 l]; after: votes [64 m][132]
    float* ps   = lhT + M_ * 132;      // [64 m][68]
    float* vbar = ps + M_ * 68;        // 128
    float* wgt  = vbar + L_;           // 64
    float* prob = wgt + M_;            // 64
    float* ncs  = prob + M_;           // 64

    int tid = threadIdx.x;
    int b = blockIdx.x & 255;          // B_ = 256
    int n = blockIdx.x >> 8;

    for (int i = tid; i < T_ * L_; i += 128) lhT[i] = g_lh[i];  // [t*128 + l]
    {
        const float* src = g_priors + ((size_t)(n * B_ + b) * M_) * T_;
        for (int i = tid; i < M_ * T_; i += 128) ps[(i >> 6) * 68 + (i & 63)] = src[i];
    }
    __syncthreads();

    unsigned lhb = (unsigned)__cvta_generic_to_shared(lhT);
    unsigned psb = (unsigned)__cvta_generic_to_shared(ps);
    int lx = tid & 15;                 // l quads: 4lx..+3, 64+4lx..+3
    int my = tid >> 4;                 // m = my*8 .. +7
    unsigned hA = lhb + (unsigned)lx * 16u;        // quad A
    unsigned hB = hA + 256u;                       // quad B (l+64)
    unsigned prow = psb + (unsigned)my * 2176u;    // my*8 rows * 272B

    unsigned long long acc[8][4];
    #pragma unroll
    for (int i = 0; i < 8; ++i)
        #pragma unroll
        for (int j = 0; j < 4; ++j) acc[i][j] = 0ull;

    #pragma unroll 1
    for (int tq = 0; tq < 16; ++tq) {  // t = 4tq .. 4tq+3
        float4 pv[8];
        #pragma unroll
        for (int i = 0; i < 8; ++i)
            asm volatile("ld.shared.v4.f32 {%0,%1,%2,%3},[%4];"
                         : "=f"(pv[i].x), "=f"(pv[i].y), "=f"(pv[i].z), "=f"(pv[i].w)
                         : "r"(prow + (unsigned)i * 272u + (unsigned)tq * 16u));
        #pragma unroll
        for (int dd = 0; dd < 4; ++dd) {
            unsigned long long ha0, ha1, hb0, hb1;
            unsigned rowoff = (unsigned)(tq * 4 + dd) * 512u;
            asm volatile("ld.shared.v2.b64 {%0,%1},[%2];" : "=l"(ha0), "=l"(ha1) : "r"(hA + rowoff));
            asm volatile("ld.shared.v2.b64 {%0,%1},[%2];" : "=l"(hb0), "=l"(hb1) : "r"(hB + rowoff));
            #pragma unroll
            for (int i = 0; i < 8; ++i) {
                float xs = (dd == 0) ? pv[i].x : (dd == 1) ? pv[i].y
                         : (dd == 2) ? pv[i].z : pv[i].w;
                unsigned long long pa;
                asm("mov.b64 %0, {%1,%1};" : "=l"(pa) : "f"(xs));
                asm("fma.rn.f32x2 %0, %1, %2, %0;" : "+l"(acc[i][0]) : "l"(pa), "l"(ha0));
                asm("fma.rn.f32x2 %0, %1, %2, %0;" : "+l"(acc[i][1]) : "l"(pa), "l"(ha1));
                asm("fma.rn.f32x2 %0, %1, %2, %0;" : "+l"(acc[i][2]) : "l"(pa), "l"(hb0));
                asm("fma.rn.f32x2 %0, %1, %2, %0;" : "+l"(acc[i][3]) : "l"(pa), "l"(hb1));
            }
        }
    }
    __syncthreads();  // all lhT reads done -> region dead, reuse as votes [m][132]

    // sigmoid + store votes: acc[i][j] -> l = (j>=2)*64 + 4lx + (j&1)*2 .. +1
    #pragma unroll
    for (int i = 0; i < 8; ++i) {
        int m = my * 8 + i;
        #pragma unroll
        for (int j = 0; j < 4; ++j) {
            float v0, v1;
            asm("mov.b64 {%0,%1}, %2;" : "=f"(v0), "=f"(v1) : "l"(acc[i][j]));
            v0 = 1.0f / (1.0f + __expf(-v0));
            v1 = 1.0f / (1.0f + __expf(-v1));
            int l = ((j >> 1) << 6) + 4 * lx + ((j & 1) << 1);
            unsigned a = lhb + (unsigned)(m * 132 + l) * 4u;
            asm volatile("st.shared.v2.f32 [%0],{%1,%2};" :: "r"(a), "f"(v0), "f"(v1) : "memory");
        }
    }
    __syncthreads();
    float* vt = lhT;  // [m][132]

    // vbar[l] = mean over m  (lane-contiguous columns: conflict-free)
    {
        float s = 0.f;
        #pragma unroll 8
        for (int m = 0; m < M_; ++m) s += vt[m * 132 + tid];
        vbar[tid] = s * (1.0f / M_);
    }
    __syncthreads();

    // dispersion + relu(thread^2 - dis): 4 threads per m, l = 4k + q.
    // 128 threads cover 32 m's per rep -> 2 reps for M_=64.
    // banks (m*132 + 4k + q) % 32 = (4m + 4k + q) % 32 -> all 32 distinct.
    #pragma unroll 1
    for (int rep = 0; rep < 2; ++rep) {
        int m = rep * 32 + (tid >> 2), q = tid & 3;
        float s = 0.f;
        #pragma unroll 8
        for (int k = 0; k < 32; ++k) {
            int l = 4 * k + q;
            float dv = vt[m * 132 + l] - vbar[l];
            s = fmaf(dv, dv, s);
        }
        s += __shfl_xor_sync(0xffffffffu, s, 1);
        s += __shfl_xor_sync(0xffffffffu, s, 2);
        if (q == 0) {
            float tw = thr[m * N_ + n];
            wgt[m] = fmaxf(fmaf(tw, tw, -s * (1.0f / L_)), 0.0f);
        }
    }
    __syncthreads();

    // softmax over M
    if (tid < M_) {
        float mxw = -3.0e38f;
        #pragma unroll 8
        for (int m = 0; m < M_; ++m) mxw = fmaxf(mxw, wgt[m]);
        prob[tid] = __expf(wgt[tid] - mxw);
    }
    __syncthreads();

    // next_caps
    if (tid < T_) {
        float psum = 0.f;
        #pragma unroll 8
        for (int m = 0; m < M_; ++m) psum += prob[m];
        float nc = 0.f;
        #pragma unroll 8
        for (int m = 0; m < M_; ++m) nc = fmaf(prob[m], ps[m * 68 + tid], nc);
        ncs[tid] = nc / psum;
    }
    __syncthreads();

    // layernorm over T
    if (tid < T_) {
        float mu = 0.f;
        #pragma unroll 8
        for (int t2 = 0; t2 < T_; ++t2) mu += ncs[t2];
        mu *= (1.0f / T_);
        float var = 0.f;
        #pragma unroll 8
        for (int t2 = 0; t2 < T_; ++t2) { float dv = ncs[t2] - mu; var = fmaf(dv, dv, var); }
        var *= (1.0f / T_);
        float y = (ncs[tid] - mu) * rsqrtf(var + 1e-5f) * gamma[tid] + beta[tid];
        out[((size_t)b * N_ + n) * T_ + tid] = y;
    }
}

// ---------------------------------------------------------------------------
// Launch
// ---------------------------------------------------------------------------
extern "C" void kernel_launch(void* const* d_in, const int* in_sizes, int n_in,
                              void* d_out, int out_size) {
    const float* x      = (const float*)d_in[0];
    const float* rw     = (const float*)d_in[1];
    const float* thr    = (const float*)d_in[2];
    const float* leaves = (const float*)d_in[3];
    const float* gamma  = (const float*)d_in[4];
    const float* beta   = (const float*)d_in[5];
    float* out = (float*)d_out;

    k_leaves<<<1, 128>>>(leaves);
    k_entmax<<<M_ * N_, 128>>>(rw);
    k_priors<<<M_ * N_, 256>>>(x);

    const int smem_route = (M_ * 132 + M_ * 68 + L_ + 3 * M_) * 4;  // 52480 B
    static int attr_set = 0;
    if (!attr_set) {
        cudaFuncSetAttribute(k_route, cudaFuncAttributeMaxDynamicSharedMemorySize, smem_route);
        attr_set = 1;
    }
    k_route<<<B_ * N_, 128, smem_route>>>(thr, gamma, beta, out);
}

// round 8
// speedup vs baseline: 1.7027x; 1.0710x over previous
#include <cuda_runtime.h>
#include <math.h>

#define B_ 256
#define M_ 64
#define N_ 32
#define D_ 128
#define T_ 64
#define L_ 128

// Scratch (allocation-free: __device__ globals)
__device__ float g_WT[(size_t)M_ * N_ * D_ * T_];      // entmax weights, [mn][d][t]
__device__ float g_priors[(size_t)N_ * B_ * M_ * T_];  // priors, [n][b][m][t]
__device__ float g_lh[T_ * L_];                        // normalized leaves, TRANSPOSED [t][l]

// ---------------------------------------------------------------------------
// K0: normalize routing_leaves rows; store transposed [t][l]
// ---------------------------------------------------------------------------
__global__ void k_leaves(const float* __restrict__ leaves) {
    int l = threadIdx.x;
    if (l < L_) {
        float s = 0.f;
        #pragma unroll
        for (int t = 0; t < T_; ++t) { float v = leaves[l * T_ + t]; s = fmaf(v, v, s); }
        float inv = 1.0f / fmaxf(sqrtf(s), 1e-12f);
        #pragma unroll
        for (int t = 0; t < T_; ++t) g_lh[t * L_ + l] = leaves[l * T_ + t] * inv;
    }
}

// ---------------------------------------------------------------------------
// K1: exact 1.5-entmax over D per (m,n,t) column via 12 bisection + 2 Newton
//     on f(tau) = sum max(z - tau, 0)^2 = 1. 2 threads/column.
//     Output layout: g_WT[mn][d][t].
// ---------------------------------------------------------------------------
__global__ __launch_bounds__(128) void k_entmax(const float* __restrict__ rw) {
    __shared__ float sm[D_ * 65];  // [d][t] pad 65
    int mn = blockIdx.x;
    const float* src = rw + (size_t)mn * D_ * T_;
    for (int i = threadIdx.x; i < D_ * T_; i += 128)
        sm[(i >> 6) * 65 + (i & 63)] = src[i];
    __syncthreads();

    int col = threadIdx.x >> 1, half = threadIdx.x & 1;
    float z[64];
    float mx = -3.0e38f;
    #pragma unroll
    for (int k = 0; k < 64; ++k) {
        z[k] = sm[(half * 64 + k) * 65 + col];
        mx = fmaxf(mx, z[k]);
    }
    mx = fmaxf(mx, __shfl_xor_sync(0xffffffffu, mx, 1));
    #pragma unroll
    for (int k = 0; k < 64; ++k) z[k] = 0.5f * z[k] - 0.5f * mx;

    float lo = -1.0f, hi = 0.0f;
    #pragma unroll 1
    for (int it = 0; it < 12; ++it) {
        float mid = 0.5f * (lo + hi);
        float s0 = 0.f, s1 = 0.f, s2 = 0.f, s3 = 0.f;
        #pragma unroll
        for (int k = 0; k < 64; k += 4) {
            float a0 = fmaxf(z[k + 0] - mid, 0.f); s0 = fmaf(a0, a0, s0);
            float a1 = fmaxf(z[k + 1] - mid, 0.f); s1 = fmaf(a1, a1, s1);
            float a2 = fmaxf(z[k + 2] - mid, 0.f); s2 = fmaf(a2, a2, s2);
            float a3 = fmaxf(z[k + 3] - mid, 0.f); s3 = fmaf(a3, a3, s3);
        }
        float s = (s0 + s1) + (s2 + s3);
        s += __shfl_xor_sync(0xffffffffu, s, 1);
        if (s >= 1.0f) lo = mid; else hi = mid;
    }
    float tau = 0.5f * (lo + hi);
    #pragma unroll 1
    for (int it = 0; it < 2; ++it) {
        float f0 = 0.f, f1 = 0.f, g0 = 0.f, g1 = 0.f;
        #pragma unroll
        for (int k = 0; k < 64; k += 2) {
            float a0 = fmaxf(z[k + 0] - tau, 0.f); f0 = fmaf(a0, a0, f0); g0 += a0;
            float a1 = fmaxf(z[k + 1] - tau, 0.f); f1 = fmaf(a1, a1, f1); g1 += a1;
        }
        float f = f0 + f1, g = g0 + g1;
        f += __shfl_xor_sync(0xffffffffu, f, 1);
        g += __shfl_xor_sync(0xffffffffu, g, 1);
        tau += (f - 1.0f) / fmaxf(2.0f * g, 1e-12f);
    }

    #pragma unroll
    for (int k = 0; k < 64; ++k) {
        float a = fmaxf(z[k] - tau, 0.f);
        sm[(half * 64 + k) * 65 + col] = a * a;
    }
    __syncthreads();
    float* dst = g_WT + (size_t)mn * D_ * T_;  // [d][t]
    for (int i = threadIdx.x; i < D_ * T_; i += 128)
        dst[i] = sm[(i >> 6) * 65 + (i & 63)];
}

// ---------------------------------------------------------------------------
// K2: priors[b,m,n,t] = sum_d x[b,m,d] * W[m,n,d,t].
//     Grid = 2 * M_*N_: blockIdx = mn*2 + chunk; each block does a 128-b
//     chunk of the [256 b x 64 t] GEMM (K = 128). W staged [d][64] (no pad).
//     Thread tile 4 b x 8 t (two contiguous quads t = 4tx..+3, 32+4tx..+3),
//     packed fma.rn.f32x2. Output [n][b][m][t].
// ---------------------------------------------------------------------------
__global__ __launch_bounds__(256) void k_priors(const float* __restrict__ x) {
    __shared__ __align__(16) float ws[D_ * 64];  // [d][t], rows 256B
    int mn = blockIdx.x >> 1;
    int chunk = blockIdx.x & 1;
    int m = mn >> 5, n = mn & 31;
    {
        const float* wsrc = g_WT + (size_t)mn * D_ * T_;  // [d][t] same layout
        for (int i = threadIdx.x; i < D_ * T_; i += 256) ws[i] = wsrc[i];
    }
    __syncthreads();
    unsigned wsb = (unsigned)__cvta_generic_to_shared(ws);
    int tx = threadIdx.x & 7;    // t quads: 4tx..+3 and 32+4tx..+3
    int ty = threadIdx.x >> 3;   // b-group (0..31)
    unsigned wA = wsb + (unsigned)tx * 16u;        // quad A
    unsigned wB = wA + 128u;                       // quad B (t+32)

    int b0 = chunk * 128 + ty * 4;
    unsigned long long acc[4][4];
    #pragma unroll
    for (int bi = 0; bi < 4; ++bi)
        #pragma unroll
        for (int j = 0; j < 4; ++j) acc[bi][j] = 0ull;

    const float4* xr[4];
    #pragma unroll
    for (int bi = 0; bi < 4; ++bi)
        xr[bi] = reinterpret_cast<const float4*>(x + ((size_t)(b0 + bi) * M_ + m) * D_);

    #pragma unroll 2
    for (int dq = 0; dq < 32; ++dq) {
        float4 xv[4];
        #pragma unroll
        for (int bi = 0; bi < 4; ++bi) xv[bi] = __ldg(&xr[bi][dq]);
        #pragma unroll
        for (int dd = 0; dd < 4; ++dd) {
            unsigned long long a01, a23, b01, b23;
            unsigned rowoff = (unsigned)(dq * 4 + dd) * 256u;
            asm volatile("ld.shared.v2.b64 {%0,%1},[%2];" : "=l"(a01), "=l"(a23) : "r"(wA + rowoff));
            asm volatile("ld.shared.v2.b64 {%0,%1},[%2];" : "=l"(b01), "=l"(b23) : "r"(wB + rowoff));
            #pragma unroll
            for (int bi = 0; bi < 4; ++bi) {
                float xs = (dd == 0) ? xv[bi].x : (dd == 1) ? xv[bi].y
                         : (dd == 2) ? xv[bi].z : xv[bi].w;
                unsigned long long xb;
                asm("mov.b64 %0, {%1,%1};" : "=l"(xb) : "f"(xs));
                asm("fma.rn.f32x2 %0, %1, %2, %0;" : "+l"(acc[bi][0]) : "l"(xb), "l"(a01));
                asm("fma.rn.f32x2 %0, %1, %2, %0;" : "+l"(acc[bi][1]) : "l"(xb), "l"(a23));
                asm("fma.rn.f32x2 %0, %1, %2, %0;" : "+l"(acc[bi][2]) : "l"(xb), "l"(b01));
                asm("fma.rn.f32x2 %0, %1, %2, %0;" : "+l"(acc[bi][3]) : "l"(xb), "l"(b23));
            }
        }
    }
    #pragma unroll
    for (int bi = 0; bi < 4; ++bi) {
        float4 o0, o1;
        asm("mov.b64 {%0,%1}, %2;" : "=f"(o0.x), "=f"(o0.y) : "l"(acc[bi][0]));
        asm("mov.b64 {%0,%1}, %2;" : "=f"(o0.z), "=f"(o0.w) : "l"(acc[bi][1]));
        asm("mov.b64 {%0,%1}, %2;" : "=f"(o1.x), "=f"(o1.y) : "l"(acc[bi][2]));
        asm("mov.b64 {%0,%1}, %2;" : "=f"(o1.z), "=f"(o1.w) : "l"(acc[bi][3]));
        float* dst = g_priors + ((size_t)(n * B_ + b0 + bi) * M_ + m) * T_;
        *reinterpret_cast<float4*>(dst + 4 * tx) = o0;
        *reinterpret_cast<float4*>(dst + 32 + 4 * tx) = o1;
    }
}

// ---------------------------------------------------------------------------
// K3: per (b,n) block (256 threads, 8 warps): votes GEMM (4m x 8l f32x2
//     tiles) + sigmoid, mean-over-M, dispersion, relu, softmax over M,
//     next_caps, LN. lh staged [t][128]; votes overwrite it (stride 132)
//     after the GEMM. Dynamic smem 52480 B -> 3-4 blocks/SM, 24-32 warps.
// ---------------------------------------------------------------------------
__global__ __launch_bounds__(256) void k_route(
    const float* __restrict__ thr, const float* __restrict__ gamma,
    const float* __restrict__ beta, float* __restrict__ out)
{
    extern __shared__ float smd[];
    float* lhT  = smd;                 // GEMM: [64 t][128 l]; after: votes [64 m][132]
    float* ps   = lhT + M_ * 132;      // [64 m][68]
    float* vbar = ps + M_ * 68;        // 128
    float* wgt  = vbar + L_;           // 64
    float* prob = wgt + M_;            // 64
    float* ncs  = prob + M_;           // 64

    int tid = threadIdx.x;
    int b = blockIdx.x & 255;          // B_ = 256
    int n = blockIdx.x >> 8;

    {   // lh: 8192 floats, contiguous, float4
        const float4* s4 = reinterpret_cast<const float4*>(g_lh);
        float4* d4 = reinterpret_cast<float4*>(lhT);
        for (int i = tid; i < (T_ * L_) / 4; i += 256) d4[i] = s4[i];
    }
    {   // ps: 4096 floats, src contiguous, dst stride 68 (float4-aligned)
        const float4* s4 = reinterpret_cast<const float4*>(
            g_priors + ((size_t)(n * B_ + b) * M_) * T_);
        for (int i = tid; i < M_ * (T_ / 4); i += 256) {
            int r = i >> 4, c = i & 15;  // row, float4-col
            reinterpret_cast<float4*>(ps + r * 68)[c] = s4[i];
        }
    }
    __syncthreads();

    unsigned lhb = (unsigned)__cvta_generic_to_shared(lhT);
    unsigned psb = (unsigned)__cvta_generic_to_shared(ps);
    int lx = tid & 15;                 // l quads: 4lx..+3, 64+4lx..+3
    int my = tid >> 4;                 // m = 4*my .. +3  (my 0..15)
    unsigned hA = lhb + (unsigned)lx * 16u;        // quad A
    unsigned hB = hA + 256u;                       // quad B (l+64)
    unsigned prow = psb + (unsigned)my * 1088u;    // my*4 rows * 272B

    unsigned long long acc[4][4];
    #pragma unroll
    for (int i = 0; i < 4; ++i)
        #pragma unroll
        for (int j = 0; j < 4; ++j) acc[i][j] = 0ull;

    #pragma unroll 1
    for (int tq = 0; tq < 16; ++tq) {  // t = 4tq .. 4tq+3
        float4 pv[4];
        #pragma unroll
        for (int i = 0; i < 4; ++i)
            asm volatile("ld.shared.v4.f32 {%0,%1,%2,%3},[%4];"
                         : "=f"(pv[i].x), "=f"(pv[i].y), "=f"(pv[i].z), "=f"(pv[i].w)
                         : "r"(prow + (unsigned)i * 272u + (unsigned)tq * 16u));
        #pragma unroll
        for (int dd = 0; dd < 4; ++dd) {
            unsigned long long ha0, ha1, hb0, hb1;
            unsigned rowoff = (unsigned)(tq * 4 + dd) * 512u;
            asm volatile("ld.shared.v2.b64 {%0,%1},[%2];" : "=l"(ha0), "=l"(ha1) : "r"(hA + rowoff));
            asm volatile("ld.shared.v2.b64 {%0,%1},[%2];" : "=l"(hb0), "=l"(hb1) : "r"(hB + rowoff));
            #pragma unroll
            for (int i = 0; i < 4; ++i) {
                float xs = (dd == 0) ? pv[i].x : (dd == 1) ? pv[i].y
                         : (dd == 2) ? pv[i].z : pv[i].w;
                unsigned long long pa;
                asm("mov.b64 %0, {%1,%1};" : "=l"(pa) : "f"(xs));
                asm("fma.rn.f32x2 %0, %1, %2, %0;" : "+l"(acc[i][0]) : "l"(pa), "l"(ha0));
                asm("fma.rn.f32x2 %0, %1, %2, %0;" : "+l"(acc[i][1]) : "l"(pa), "l"(ha1));
                asm("fma.rn.f32x2 %0, %1, %2, %0;" : "+l"(acc[i][2]) : "l"(pa), "l"(hb0));
                asm("fma.rn.f32x2 %0, %1, %2, %0;" : "+l"(acc[i][3]) : "l"(pa), "l"(hb1));
            }
        }
    }
    __syncthreads();  // all lhT reads done -> region dead, reuse as votes [m][132]

    // sigmoid + store votes: acc[i][j] -> m = 4*my+i, l = (j>=2)*64 + 4lx + (j&1)*2
    #pragma unroll
    for (int i = 0; i < 4; ++i) {
        int m = 4 * my + i;
        #pragma unroll
        for (int j = 0; j < 4; ++j) {
            float v0, v1;
            asm("mov.b64 {%0,%1}, %2;" : "=f"(v0), "=f"(v1) : "l"(acc[i][j]));
            v0 = 1.0f / (1.0f + __expf(-v0));
            v1 = 1.0f / (1.0f + __expf(-v1));
            int l = ((j >> 1) << 6) + 4 * lx + ((j & 1) << 1);
            unsigned a = lhb + (unsigned)(m * 132 + l) * 4u;
            asm volatile("st.shared.v2.f32 [%0],{%1,%2};" :: "r"(a), "f"(v0), "f"(v1) : "memory");
        }
    }
    __syncthreads();
    float* vt = lhT;  // [m][132]

    // vbar[l] = mean over m  (lane-contiguous columns: conflict-free)
    if (tid < L_) {
        float s = 0.f;
        #pragma unroll 8
        for (int m = 0; m < M_; ++m) s += vt[m * 132 + tid];
        vbar[tid] = s * (1.0f / M_);
    }
    __syncthreads();

    // dispersion + relu(thread^2 - dis): 4 threads per m, single pass (256 thr).
    // banks (m*132 + 4k + q) % 32 = (4m + 4k + q) % 32 -> all 32 distinct.
    {
        int m = tid >> 2, q = tid & 3;
        float s = 0.f;
        #pragma unroll 8
        for (int k = 0; k < 32; ++k) {
            int l = 4 * k + q;
            float dv = vt[m * 132 + l] - vbar[l];
            s = fmaf(dv, dv, s);
        }
        s += __shfl_xor_sync(0xffffffffu, s, 1);
        s += __shfl_xor_sync(0xffffffffu, s, 2);
        if (q == 0) {
            float tw = thr[m * N_ + n];
            wgt[m] = fmaxf(fmaf(tw, tw, -s * (1.0f / L_)), 0.0f);
        }
    }
    __syncthreads();

    // softmax over M
    if (tid < M_) {
        float mxw = -3.0e38f;
        #pragma unroll 8
        for (int m = 0; m < M_; ++m) mxw = fmaxf(mxw, wgt[m]);
        prob[tid] = __expf(wgt[tid] - mxw);
    }
    __syncthreads();

    // next_caps
    if (tid < T_) {
        float psum = 0.f;
        #pragma unroll 8
        for (int m = 0; m < M_; ++m) psum += prob[m];
        float nc = 0.f;
        #pragma unroll 8
        for (int m = 0; m < M_; ++m) nc = fmaf(prob[m], ps[m * 68 + tid], nc);
        ncs[tid] = nc / psum;
    }
    __syncthreads();

    // layernorm over T
    if (tid < T_) {
        float mu = 0.f;
        #pragma unroll 8
        for (int t2 = 0; t2 < T_; ++t2) mu += ncs[t2];
        mu *= (1.0f / T_);
        float var = 0.f;
        #pragma unroll 8
        for (int t2 = 0; t2 < T_; ++t2) { float dv = ncs[t2] - mu; var = fmaf(dv, dv, var); }
        var *= (1.0f / T_);
        float y = (ncs[tid] - mu) * rsqrtf(var + 1e-5f) * gamma[tid] + beta[tid];
        out[((size_t)b * N_ + n) * T_ + tid] = y;
    }
}

// ---------------------------------------------------------------------------
// Launch
// ---------------------------------------------------------------------------
extern "C" void kernel_launch(void* const* d_in, const int* in_sizes, int n_in,
                              void* d_out, int out_size) {
    const float* x      = (const float*)d_in[0];
    const float* rw     = (const float*)d_in[1];
    const float* thr    = (const float*)d_in[2];
    const float* leaves = (const float*)d_in[3];
    const float* gamma  = (const float*)d_in[4];
    const float* beta   = (const float*)d_in[5];
    float* out = (float*)d_out;

    k_leaves<<<1, 128>>>(leaves);
    k_entmax<<<M_ * N_, 128>>>(rw);
    k_priors<<<M_ * N_ * 2, 256>>>(x);

    const int smem_route = (M_ * 132 + M_ * 68 + L_ + 3 * M_) * 4;  // 52480 B
    static int attr_set = 0;
    if (!attr_set) {
        cudaFuncSetAttribute(k_route, cudaFuncAttributeMaxDynamicSharedMemorySize, smem_route);
        attr_set = 1;
    }
    k_route<<<B_ * N_, 256, smem_route>>>(thr, gamma, beta, out);
}